// round 3
// baseline (speedup 1.0000x reference)
#include <cuda_runtime.h>
#include <cstdint>

#define EPSV  1e-5f
#define SLOPE 0.01f

// ---------------- scratch (device globals; no allocation allowed) ----------
__device__ float g_h1[32u * 256u * 1024u];   // after layer1
__device__ float g_h2[32u * 512u * 512u];    // after layer2
__device__ float g_h3[32u * 512u * 256u];    // after layer3
__device__ float g_h4[32u * 128u * 256u];    // after layer4
__device__ float g_fnorm[8192];
__device__ float g_enorm[4096];
__device__ float g_pval[8192 * 32];
__device__ int   g_pidx[8192 * 32];
// fallbacks if the harness output layout differs from codes||dist
__device__ float g_dist_scratch[8192ull * 4096ull];
__device__ float g_codes_scratch[8192];

// ---------------------------------------------------------------------------
// Conv1d(k=3, pad=1) + BatchNorm(eval) + LeakyReLU as implicit GEMM.
//   C[o, n] = sum_{kk} W[o, kk] * X[kk, n],  kk = i*3+k,  n = b*LOUT + l
//   X[kk, n] = in[b, i, STRIDE*l + k - 1]  (zero padded)
// Block tile 128x128, K tile 16, 256 threads, 8x8 per-thread micro-tile.
// ---------------------------------------------------------------------------
template <int IC, int OC, int LIN, int LOUT, int STRIDE>
__global__ __launch_bounds__(256)
void conv_bn_lrelu(const float* __restrict__ in,   // [B, IC, LIN]
                   const float* __restrict__ w,    // [OC, IC*3]
                   const float* __restrict__ bias, // [OC]
                   const float* __restrict__ gg,
                   const float* __restrict__ be,
                   const float* __restrict__ mm,
                   const float* __restrict__ vv,
                   float* __restrict__ out)        // [B, OC, LOUT]
{
    constexpr int KD = IC * 3;
    const int n0 = blockIdx.x * 128;        // LOUT multiple of 128 => tile stays
    const int b  = n0 / LOUT;               // inside one batch element
    const int l0 = n0 % LOUT;
    const int o0 = blockIdx.y * 128;

    __shared__ float As[16][132];           // [k][o] transposed, padded
    __shared__ float Bs[16][132];           // [k][n], padded

    const int tid = threadIdx.x;
    const int tx = tid & 15;                // n micro-tile
    const int ty = tid >> 4;                // o micro-tile

    float acc[8][8];
#pragma unroll
    for (int i = 0; i < 8; i++)
#pragma unroll
        for (int j = 0; j < 8; j++) acc[i][j] = 0.f;

    const float* __restrict__ inb = in + (size_t)b * IC * LIN;

    for (int k0 = 0; k0 < KD; k0 += 16) {
        // --- load A tile (weights) 128(o) x 16(k) ---
#pragma unroll
        for (int j = 0; j < 8; j++) {
            int idx = tid + 256 * j;
            int ol  = idx >> 4;
            int kl  = idx & 15;
            As[kl][ol] = w[(size_t)(o0 + ol) * KD + (k0 + kl)];
        }
        // --- load B tile (im2col gather) 16(k) x 128(n) ---
#pragma unroll
        for (int j = 0; j < 8; j++) {
            int idx = tid + 256 * j;
            int kl  = idx >> 7;
            int nl  = idx & 127;
            int kk  = k0 + kl;
            int ci  = kk / 3;
            int kw  = kk - ci * 3;
            int pos = STRIDE * (l0 + nl) + kw - 1;
            float v = 0.f;
            if (pos >= 0 && pos < LIN) v = inb[(size_t)ci * LIN + pos];
            Bs[kl][nl] = v;
        }
        __syncthreads();

#pragma unroll
        for (int k = 0; k < 16; k++) {
            float a[8], bb[8];
            *(float4*)&a[0]  = *(const float4*)&As[k][ty * 8];
            *(float4*)&a[4]  = *(const float4*)&As[k][ty * 8 + 4];
            *(float4*)&bb[0] = *(const float4*)&Bs[k][tx * 8];
            *(float4*)&bb[4] = *(const float4*)&Bs[k][tx * 8 + 4];
#pragma unroll
            for (int i = 0; i < 8; i++)
#pragma unroll
                for (int j = 0; j < 8; j++)
                    acc[i][j] = fmaf(a[i], bb[j], acc[i][j]);
        }
        __syncthreads();
    }

    // --- fused BN + LeakyReLU epilogue ---
#pragma unroll
    for (int i = 0; i < 8; i++) {
        int o = o0 + ty * 8 + i;
        float alpha = gg[o] * rsqrtf(vv[o] + EPSV);
        float beta  = (bias[o] - mm[o]) * alpha + be[o];
        float* op = out + (size_t)b * OC * LOUT + (size_t)o * LOUT + l0 + tx * 8;
        float4 r0, r1;
#pragma unroll
        for (int j = 0; j < 8; j++) {
            float t = acc[i][j] * alpha + beta;
            t = (t >= 0.f) ? t : SLOPE * t;
            if (j < 4) ((float*)&r0)[j] = t; else ((float*)&r1)[j - 4] = t;
        }
        *(float4*)op       = r0;
        *(float4*)(op + 4) = r1;
    }
}

// ---------------------------------------------------------------------------
// precompute ||emb_k||^2 (one thread per code)
// ---------------------------------------------------------------------------
__global__ void enorm_kernel(const float* __restrict__ emb)
{
    int k = blockIdx.x * 256 + threadIdx.x;     // 4096 total
    if (k >= 4096) return;
    const float* e = emb + (size_t)k * 128;
    float s = 0.f;
#pragma unroll 8
    for (int d = 0; d < 128; d++) s = fmaf(e[d], e[d], s);
    g_enorm[k] = s;
}

// precompute ||flat_n||^2, flat[n, d] = h4[b, d, l], n = b*256 + l
__global__ void fnorm_kernel()
{
    int n = blockIdx.x * 256 + threadIdx.x;     // 8192 total
    int b = n >> 8, l = n & 255;
    float s = 0.f;
#pragma unroll 8
    for (int d = 0; d < 128; d++) {
        float x = g_h4[((size_t)b * 128 + d) * 256 + l];
        s = fmaf(x, x, s);
    }
    g_fnorm[n] = s;
}

// ---------------------------------------------------------------------------
// VQ distance GEMM: dist[r, c] = fnorm[r] + enorm[c] - 2 * flat[r,:].emb[c,:]
// M=8192 rows, N=4096 codes, K=128. Fused per-block partial argmin.
// ---------------------------------------------------------------------------
__global__ __launch_bounds__(256)
void vq_dist(const float* __restrict__ emb, float* __restrict__ dist_out)
{
    const int c0 = blockIdx.x * 128;   // code tile (32 tiles)
    const int r0 = blockIdx.y * 128;   // row  tile (64 tiles)

    __shared__ float As[16][132];      // [d][r]
    __shared__ float Bs[16][132];      // [d][c]
    __shared__ float s_val[128 * 16];
    __shared__ int   s_idx[128 * 16];

    const int tid = threadIdx.x;
    const int tx = tid & 15;           // c micro-tile
    const int ty = tid >> 4;           // r micro-tile

    float acc[8][8];
#pragma unroll
    for (int i = 0; i < 8; i++)
#pragma unroll
        for (int j = 0; j < 8; j++) acc[i][j] = 0.f;

    for (int k0 = 0; k0 < 128; k0 += 16) {
        // A[r, d] = h4[b, d, l]
#pragma unroll
        for (int j = 0; j < 8; j++) {
            int idx = tid + 256 * j;
            int rl  = idx >> 4;
            int kl  = idx & 15;
            int r   = r0 + rl;
            int b   = r >> 8, l = r & 255;
            As[kl][rl] = g_h4[((size_t)b * 128 + (k0 + kl)) * 256 + l];
        }
        // B[d, c] = emb[c*128 + d]
#pragma unroll
        for (int j = 0; j < 8; j++) {
            int idx = tid + 256 * j;
            int cl  = idx >> 4;
            int kl  = idx & 15;
            Bs[kl][cl] = emb[(size_t)(c0 + cl) * 128 + (k0 + kl)];
        }
        __syncthreads();

#pragma unroll
        for (int k = 0; k < 16; k++) {
            float a[8], bb[8];
            *(float4*)&a[0]  = *(const float4*)&As[k][ty * 8];
            *(float4*)&a[4]  = *(const float4*)&As[k][ty * 8 + 4];
            *(float4*)&bb[0] = *(const float4*)&Bs[k][tx * 8];
            *(float4*)&bb[4] = *(const float4*)&Bs[k][tx * 8 + 4];
#pragma unroll
            for (int i = 0; i < 8; i++)
#pragma unroll
                for (int j = 0; j < 8; j++)
                    acc[i][j] = fmaf(a[i], bb[j], acc[i][j]);
        }
        __syncthreads();
    }

    // epilogue: dist values + per-thread argmin over its 8 columns
#pragma unroll
    for (int i = 0; i < 8; i++) {
        int r = r0 + ty * 8 + i;
        float fn = g_fnorm[r];
        float bv = 3.0e38f;
        int   bi = c0;
        float* dp = dist_out + (size_t)r * 4096 + c0 + tx * 8;
        float4 o0v, o1v;
#pragma unroll
        for (int j = 0; j < 8; j++) {
            int   c  = c0 + tx * 8 + j;
            float dv = fn + g_enorm[c] - 2.f * acc[i][j];
            if (j < 4) ((float*)&o0v)[j] = dv; else ((float*)&o1v)[j - 4] = dv;
            if (dv < bv) { bv = dv; bi = c; }
        }
        *(float4*)dp       = o0v;
        *(float4*)(dp + 4) = o1v;
        s_val[(ty * 8 + i) * 16 + tx] = bv;
        s_idx[(ty * 8 + i) * 16 + tx] = bi;
    }
    __syncthreads();

    // per-row reduce over the 16 tx lanes (ascending -> lowest index on ties)
    if (tid < 128) {
        float bv = s_val[tid * 16];
        int   bi = s_idx[tid * 16];
#pragma unroll
        for (int t = 1; t < 16; t++) {
            float v = s_val[tid * 16 + t];
            if (v < bv) { bv = v; bi = s_idx[tid * 16 + t]; }
        }
        g_pval[(size_t)(r0 + tid) * 32 + blockIdx.x] = bv;
        g_pidx[(size_t)(r0 + tid) * 32 + blockIdx.x] = bi;
    }
}

// final argmin reduce across the 32 column tiles; codes written as float
__global__ void vq_reduce(float* __restrict__ codes_out)
{
    int n = blockIdx.x * 256 + threadIdx.x;   // 8192 total
    float bv = g_pval[(size_t)n * 32];
    int   bi = g_pidx[(size_t)n * 32];
#pragma unroll
    for (int t = 1; t < 32; t++) {
        float v = g_pval[(size_t)n * 32 + t];
        if (v < bv) { bv = v; bi = g_pidx[(size_t)n * 32 + t]; }
    }
    codes_out[n] = (float)bi;
}

// ---------------------------------------------------------------------------
extern "C" void kernel_launch(void* const* d_in, const int* in_sizes, int n_in,
                              void* d_out, int out_size)
{
    const float* x   = (const float*)d_in[0];
    const float* w1  = (const float*)d_in[1];
    const float* b1  = (const float*)d_in[2];
    const float* w2  = (const float*)d_in[3];
    const float* b2  = (const float*)d_in[4];
    const float* w3  = (const float*)d_in[5];
    const float* b3  = (const float*)d_in[6];
    const float* w4  = (const float*)d_in[7];
    const float* b4  = (const float*)d_in[8];
    const float* g1  = (const float*)d_in[9];
    const float* be1 = (const float*)d_in[10];
    const float* m1  = (const float*)d_in[11];
    const float* v1  = (const float*)d_in[12];
    const float* g2  = (const float*)d_in[13];
    const float* be2 = (const float*)d_in[14];
    const float* m2  = (const float*)d_in[15];
    const float* v2  = (const float*)d_in[16];
    const float* g3  = (const float*)d_in[17];
    const float* be3 = (const float*)d_in[18];
    const float* m3  = (const float*)d_in[19];
    const float* v3  = (const float*)d_in[20];
    const float* g4  = (const float*)d_in[21];
    const float* be4 = (const float*)d_in[22];
    const float* m4  = (const float*)d_in[23];
    const float* v4  = (const float*)d_in[24];
    const float* emb = (const float*)d_in[25];

    void *p_h1, *p_h2, *p_h3, *p_h4, *p_dist_scr, *p_codes_scr;
    cudaGetSymbolAddress(&p_h1, g_h1);
    cudaGetSymbolAddress(&p_h2, g_h2);
    cudaGetSymbolAddress(&p_h3, g_h3);
    cudaGetSymbolAddress(&p_h4, g_h4);
    cudaGetSymbolAddress(&p_dist_scr, g_dist_scratch);
    cudaGetSymbolAddress(&p_codes_scr, g_codes_scratch);

    float* h1 = (float*)p_h1;
    float* h2 = (float*)p_h2;
    float* h3 = (float*)p_h3;
    float* h4 = (float*)p_h4;

    // Output layout: reference returns (codes, dist). Default: codes||dist.
    float* out = (float*)d_out;
    float* codes_ptr;
    float* dist_ptr;
    const long long FULL = 8192LL + 8192LL * 4096LL;
    if ((long long)out_size >= FULL) {
        codes_ptr = out;
        dist_ptr  = out + 8192;
    } else if ((long long)out_size == 8192LL * 4096LL) {
        codes_ptr = (float*)p_codes_scr;
        dist_ptr  = out;
    } else {
        codes_ptr = out;
        dist_ptr  = (float*)p_dist_scr;
    }

    // Layer 1: 256 -> 256, L 2048 -> 1024, stride 2
    conv_bn_lrelu<256, 256, 2048, 1024, 2>
        <<<dim3(256, 2), 256>>>(x, w1, b1, g1, be1, m1, v1, h1);
    // Layer 2: 256 -> 512, L 1024 -> 512, stride 2
    conv_bn_lrelu<256, 512, 1024, 512, 2>
        <<<dim3(128, 4), 256>>>(h1, w2, b2, g2, be2, m2, v2, h2);
    // Layer 3: 512 -> 512, L 512 -> 256, stride 2
    conv_bn_lrelu<512, 512, 512, 256, 2>
        <<<dim3(64, 4), 256>>>(h2, w3, b3, g3, be3, m3, v3, h3);
    // Layer 4: 512 -> 128, L 256 -> 256, stride 1
    conv_bn_lrelu<512, 128, 256, 256, 1>
        <<<dim3(64, 1), 256>>>(h3, w4, b4, g4, be4, m4, v4, h4);

    enorm_kernel<<<16, 256>>>(emb);
    fnorm_kernel<<<32, 256>>>();

    vq_dist<<<dim3(32, 64), 256>>>(emb, dist_ptr);
    vq_reduce<<<32, 256>>>(codes_ptr);
}

// round 5
// speedup vs baseline: 2.2506x; 2.2506x over previous
#include <cuda_runtime.h>
#include <cuda_bf16.h>
#include <cstdint>

#define EPSV  1e-5f
#define SLOPE 0.01f

// ---------------- scratch (device globals; no allocation allowed) ----------
__device__ float g_h1[32u * 256u * 1024u];   // after layer1 [B,256,1024]
__device__ float g_h2[32u * 512u * 512u];    // after layer2 [B,512,512]
__device__ float g_h3[32u * 512u * 256u];    // after layer3 [B,512,256]
__device__ float g_flat[8192u * 128u];       // after layer4, [n, d] row-major
__device__ float g_fnorm[8192];
__device__ float g_enorm[4096];
__device__ float g_pval[8192 * 32];
__device__ int   g_pidx[8192 * 32];
// fallbacks if the harness output layout differs from codes||dist
__device__ float g_dist_scratch[8192ull * 4096ull];
__device__ float g_codes_scratch[8192];

// ===========================================================================
// mma.sync helpers (base sm_100 target: HMMA path, NOT tcgen05)
// ===========================================================================
__device__ __forceinline__ uint32_t smem_u32(const void* p) {
    uint32_t a;
    asm("{ .reg .u64 t; cvta.to.shared.u64 t, %1; cvt.u32.u64 %0, t; }"
        : "=r"(a) : "l"(p));
    return a;
}

__device__ __forceinline__ void ldsm4(uint32_t* r, uint32_t addr) {
    asm volatile("ldmatrix.sync.aligned.m8n8.x4.shared.b16 {%0,%1,%2,%3}, [%4];"
                 : "=r"(r[0]), "=r"(r[1]), "=r"(r[2]), "=r"(r[3]) : "r"(addr));
}

__device__ __forceinline__ void mma_bf16(float* c, const uint32_t* a,
                                         const uint32_t* b) {
    asm volatile(
        "mma.sync.aligned.m16n8k16.row.col.f32.bf16.bf16.f32 "
        "{%0,%1,%2,%3}, {%4,%5,%6,%7}, {%8,%9}, {%0,%1,%2,%3};"
        : "+f"(c[0]), "+f"(c[1]), "+f"(c[2]), "+f"(c[3])
        : "r"(a[0]), "r"(a[1]), "r"(a[2]), "r"(a[3]), "r"(b[0]), "r"(b[1]));
}

// byte offset of element (row, k) inside a [128 rows][32 k] bf16 tile,
// 16B-chunk XOR swizzle -> conflict-free ldmatrix (8 rows, 64B stride) & STS
__device__ __forceinline__ uint32_t toff(int row, int k) {
    return (uint32_t)(row * 64 + ((((k >> 3) ^ ((row >> 1) & 3))) << 4)
                      + ((k & 7) << 1));
}

// split (a,b) fp32 -> packed bf16x2 hi + lo
__device__ __forceinline__ uint32_t pack2(float a, float b, uint32_t& lo_pack) {
    __nv_bfloat16 ah = __float2bfloat16(a);
    __nv_bfloat16 bh = __float2bfloat16(b);
    __nv_bfloat16 al = __float2bfloat16(a - __bfloat162float(ah));
    __nv_bfloat16 bl = __float2bfloat16(b - __bfloat162float(bh));
    lo_pack = ((uint32_t)__bfloat16_as_ushort(bl) << 16) | __bfloat16_as_ushort(al);
    return ((uint32_t)__bfloat16_as_ushort(bh) << 16) | __bfloat16_as_ushort(ah);
}

// store one slot (row, kc: 8 floats) split into hi/lo tiles
__device__ __forceinline__ void sts_split(uint32_t hib, uint32_t lob,
                                          int slot, const float* v) {
    int row = slot >> 2, kc = slot & 3;
    uint32_t off = (uint32_t)(row * 64 + ((kc ^ ((row >> 1) & 3)) << 4));
    uint32_t h0, h1, h2, h3, l0, l1, l2, l3;
    h0 = pack2(v[0], v[1], l0);
    h1 = pack2(v[2], v[3], l1);
    h2 = pack2(v[4], v[5], l2);
    h3 = pack2(v[6], v[7], l3);
    asm volatile("st.shared.v4.b32 [%0], {%1,%2,%3,%4};"
                 :: "r"(hib + off), "r"(h0), "r"(h1), "r"(h2), "r"(h3) : "memory");
    asm volatile("st.shared.v4.b32 [%0], {%1,%2,%3,%4};"
                 :: "r"(lob + off), "r"(l0), "r"(l1), "r"(l2), "r"(l3) : "memory");
}

// compute one K=32 chunk: ldmatrix frags from smem + 96 mma per warp
__device__ __forceinline__ void mma_chunk(float acc[2][8][4],
                                          uint32_t aHi, uint32_t aLo,
                                          uint32_t bHi, uint32_t bLo,
                                          int wm, int wn, int lane) {
#pragma unroll
    for (int kb = 0; kb < 2; kb++) {
        const int kA = kb * 16 + ((lane >> 4) << 3);
        const int kB = kb * 16 + (lane & 8);
        uint32_t ah[2][4], al[2][4];
#pragma unroll
        for (int mi = 0; mi < 2; mi++) {
            int row = wm * 32 + mi * 16 + (lane & 7) + (lane & 8);
            uint32_t o = toff(row, kA);
            ldsm4(ah[mi], aHi + o);
            ldsm4(al[mi], aLo + o);
        }
#pragma unroll
        for (int p = 0; p < 4; p++) {
            int row = wn * 64 + p * 16 + (lane & 7) + ((lane >> 4) << 3);
            uint32_t o = toff(row, kB);
            uint32_t bh[4], bl[4];
            ldsm4(bh, bHi + o);
            ldsm4(bl, bLo + o);
#pragma unroll
            for (int mi = 0; mi < 2; mi++) {
                mma_bf16(acc[mi][2 * p],     ah[mi], bh);
                mma_bf16(acc[mi][2 * p],     ah[mi], bl);
                mma_bf16(acc[mi][2 * p],     al[mi], bh);
                mma_bf16(acc[mi][2 * p + 1], ah[mi], bh + 2);
                mma_bf16(acc[mi][2 * p + 1], ah[mi], bl + 2);
                mma_bf16(acc[mi][2 * p + 1], al[mi], bh + 2);
            }
        }
    }
}

// ===========================================================================
// Conv1d(k=3,pad=1)+BN+LeakyReLU, implicit GEMM on mma.sync bf16 split.
// !TRANS: A=weights(M=oc), B=im2col(N=pos), out[b][oc][pos].
//  TRANS: A=im2col(M=pos), B=weights(N=oc), out=flat[pos][oc].
// ===========================================================================
template <int IC, int OC, int LIN, int LOUT, int STRIDE, bool TRANS>
__global__ __launch_bounds__(256, 1)
void conv_mma(const float* __restrict__ in, const float* __restrict__ w,
              const float* __restrict__ bias,
              const float* __restrict__ gg, const float* __restrict__ be_,
              const float* __restrict__ mm, const float* __restrict__ vv,
              float* __restrict__ out) {
    constexpr int KD  = IC * 3;
    constexpr int NCH = KD / 32;
    __shared__ __align__(128) uint8_t sAh[8192], sAl[8192], sBh[8192], sBl[8192];
    __shared__ float s_alpha[128], s_beta[128];

    const int tid  = threadIdx.x;
    const int lane = tid & 31;
    const int wid  = tid >> 5;
    const int wm = wid & 3, wn = wid >> 2;
    const int n0 = blockIdx.x * 128;          // position-tile
    const int o0 = blockIdx.y * 128;          // oc-tile
    const int b  = n0 / LOUT;
    const int l0 = n0 % LOUT;
    const float* __restrict__ inb = in + (size_t)b * IC * LIN;

    const uint32_t aHi = smem_u32(sAh), aLo = smem_u32(sAl);
    const uint32_t bHi = smem_u32(sBh), bLo = smem_u32(sBl);

    if (tid < 128) {
        int o = o0 + tid;
        float a = gg[o] * rsqrtf(vv[o] + EPSV);
        s_alpha[tid] = a;
        s_beta[tid]  = (bias[o] - mm[o]) * a + be_[o];
    }

    float acc[2][8][4];
#pragma unroll
    for (int mi = 0; mi < 2; mi++)
#pragma unroll
        for (int ni = 0; ni < 8; ni++)
#pragma unroll
            for (int e = 0; e < 4; e++) acc[mi][ni][e] = 0.f;

    float vW[2][8], vX[2][8];
    auto gather = [&](int k0) {
#pragma unroll
        for (int it = 0; it < 2; it++) {
            int slot = tid + 256 * it;
            int row = slot >> 2, kc = slot & 3;
            // weights row (oc-local)
            const float4* p =
                (const float4*)(w + (size_t)(o0 + row) * KD + k0 + kc * 8);
            float4 u0 = p[0], u1 = p[1];
            vW[it][0] = u0.x; vW[it][1] = u0.y; vW[it][2] = u0.z; vW[it][3] = u0.w;
            vW[it][4] = u1.x; vW[it][5] = u1.y; vW[it][6] = u1.z; vW[it][7] = u1.w;
            // im2col row (pos-local)
            int base = STRIDE * (l0 + row) - 1;
#pragma unroll
            for (int e = 0; e < 8; e++) {
                int kk = k0 + kc * 8 + e;
                int ci = kk / 3;
                int kw = kk - ci * 3;
                int pos = base + kw;
                vX[it][e] = (pos >= 0 && pos < LIN)
                          ? inb[(size_t)ci * LIN + pos] : 0.f;
            }
        }
    };

    gather(0);
    for (int c = 0; c < NCH; c++) {
#pragma unroll
        for (int it = 0; it < 2; it++) {
            int slot = tid + 256 * it;
            if (TRANS) {
                sts_split(aHi, aLo, slot, vX[it]);
                sts_split(bHi, bLo, slot, vW[it]);
            } else {
                sts_split(aHi, aLo, slot, vW[it]);
                sts_split(bHi, bLo, slot, vX[it]);
            }
        }
        __syncthreads();
        if (c + 1 < NCH) gather((c + 1) * 32);
        mma_chunk(acc, aHi, aLo, bHi, bLo, wm, wn, lane);
        __syncthreads();
    }

    // ---- fused BN + LeakyReLU epilogue ----
#pragma unroll
    for (int mi = 0; mi < 2; mi++) {
#pragma unroll
        for (int h = 0; h < 2; h++) {
            int rl = wm * 32 + mi * 16 + h * 8 + (lane >> 2);
            if (!TRANS) {
                float alpha = s_alpha[rl], beta = s_beta[rl];
                float* op = out + ((size_t)b * OC + (o0 + rl)) * LOUT
                          + l0 + wn * 64 + (lane & 3) * 2;
#pragma unroll
                for (int ni = 0; ni < 8; ni++) {
                    float t0 = acc[mi][ni][2 * h]     * alpha + beta;
                    float t1 = acc[mi][ni][2 * h + 1] * alpha + beta;
                    t0 = (t0 >= 0.f) ? t0 : SLOPE * t0;
                    t1 = (t1 >= 0.f) ? t1 : SLOPE * t1;
                    *(float2*)(op + ni * 8) = make_float2(t0, t1);
                }
            } else {
                int n = n0 + rl;       // global flat row (position)
#pragma unroll
                for (int ni = 0; ni < 8; ni++) {
                    int ocl = wn * 64 + ni * 8 + (lane & 3) * 2;
                    float t0 = acc[mi][ni][2 * h]     * s_alpha[ocl]   + s_beta[ocl];
                    float t1 = acc[mi][ni][2 * h + 1] * s_alpha[ocl+1] + s_beta[ocl+1];
                    t0 = (t0 >= 0.f) ? t0 : SLOPE * t0;
                    t1 = (t1 >= 0.f) ? t1 : SLOPE * t1;
                    *(float2*)(out + (size_t)n * 128 + ocl) = make_float2(t0, t1);
                }
            }
        }
    }
}

// ===========================================================================
// VQ distance GEMM: dist[r,c] = fnorm[r] + enorm[c] - 2*flat_r.emb_c
// M tile 128 rows x N tile 128 codes, K=128 (4 chunks). Fused argmin.
// ===========================================================================
__global__ __launch_bounds__(256, 1)
void vq_mma(const float* __restrict__ emb, float* __restrict__ dist_out) {
    __shared__ __align__(128) uint8_t sAh[8192], sAl[8192], sBh[8192], sBl[8192];
    __shared__ float s_en[128];
    __shared__ float red_v[2][128];
    __shared__ int   red_i[2][128];

    const int tid  = threadIdx.x;
    const int lane = tid & 31;
    const int wid  = tid >> 5;
    const int wm = wid & 3, wn = wid >> 2;
    const int c0 = blockIdx.x * 128;
    const int r0 = blockIdx.y * 128;

    const uint32_t aHi = smem_u32(sAh), aLo = smem_u32(sAl);
    const uint32_t bHi = smem_u32(sBh), bLo = smem_u32(sBl);

    if (tid < 128) s_en[tid] = g_enorm[c0 + tid];

    float acc[2][8][4];
#pragma unroll
    for (int mi = 0; mi < 2; mi++)
#pragma unroll
        for (int ni = 0; ni < 8; ni++)
#pragma unroll
            for (int e = 0; e < 4; e++) acc[mi][ni][e] = 0.f;

    float vA[2][8], vB[2][8];
    auto gather = [&](int k0) {
#pragma unroll
        for (int it = 0; it < 2; it++) {
            int slot = tid + 256 * it;
            int row = slot >> 2, kc = slot & 3;
            const float4* pa =
                (const float4*)(g_flat + (size_t)(r0 + row) * 128 + k0 + kc * 8);
            float4 u0 = pa[0], u1 = pa[1];
            vA[it][0] = u0.x; vA[it][1] = u0.y; vA[it][2] = u0.z; vA[it][3] = u0.w;
            vA[it][4] = u1.x; vA[it][5] = u1.y; vA[it][6] = u1.z; vA[it][7] = u1.w;
            const float4* pb =
                (const float4*)(emb + (size_t)(c0 + row) * 128 + k0 + kc * 8);
            float4 w0 = pb[0], w1 = pb[1];
            vB[it][0] = w0.x; vB[it][1] = w0.y; vB[it][2] = w0.z; vB[it][3] = w0.w;
            vB[it][4] = w1.x; vB[it][5] = w1.y; vB[it][6] = w1.z; vB[it][7] = w1.w;
        }
    };

    gather(0);
    for (int c = 0; c < 4; c++) {
#pragma unroll
        for (int it = 0; it < 2; it++) {
            int slot = tid + 256 * it;
            sts_split(aHi, aLo, slot, vA[it]);
            sts_split(bHi, bLo, slot, vB[it]);
        }
        __syncthreads();
        if (c + 1 < 4) gather((c + 1) * 32);
        mma_chunk(acc, aHi, aLo, bHi, bLo, wm, wn, lane);
        __syncthreads();
    }

    // ---- epilogue: dist store + per-row argmin (index tie-break: lowest) ----
#pragma unroll
    for (int mi = 0; mi < 2; mi++) {
#pragma unroll
        for (int h = 0; h < 2; h++) {
            int rl = wm * 32 + mi * 16 + h * 8 + (lane >> 2);
            int r  = r0 + rl;
            float fn = g_fnorm[r];
            float bv = 3.0e38f;
            int   bi = 0x7fffffff;
            float* dp = dist_out + (size_t)r * 4096 + c0 + wn * 64 + (lane & 3) * 2;
#pragma unroll
            for (int ni = 0; ni < 8; ni++) {
                int cl = wn * 64 + ni * 8 + (lane & 3) * 2;
                float d0 = fn + s_en[cl]     - 2.f * acc[mi][ni][2 * h];
                float d1 = fn + s_en[cl + 1] - 2.f * acc[mi][ni][2 * h + 1];
                *(float2*)(dp + ni * 8) = make_float2(d0, d1);
                if (d0 < bv) { bv = d0; bi = c0 + cl; }
                if (d1 < bv) { bv = d1; bi = c0 + cl + 1; }
            }
#pragma unroll
            for (int off = 1; off <= 2; off <<= 1) {
                float ov = __shfl_xor_sync(0xffffffffu, bv, off);
                int   oi = __shfl_xor_sync(0xffffffffu, bi, off);
                if (ov < bv || (ov == bv && oi < bi)) { bv = ov; bi = oi; }
            }
            if ((lane & 3) == 0) { red_v[wn][rl] = bv; red_i[wn][rl] = bi; }
        }
    }
    __syncthreads();
    if (tid < 128) {
        float bv = red_v[0][tid];
        int   bi = red_i[0][tid];
        float ov = red_v[1][tid];
        int   oi = red_i[1][tid];
        if (ov < bv || (ov == bv && oi < bi)) { bv = ov; bi = oi; }
        g_pval[(size_t)(r0 + tid) * 32 + blockIdx.x] = bv;
        g_pidx[(size_t)(r0 + tid) * 32 + blockIdx.x] = bi;
    }
}

// ---------------------------------------------------------------------------
__global__ void enorm_kernel(const float* __restrict__ emb) {
    int k = blockIdx.x * 256 + threadIdx.x;     // 4096 total
    const float* e = emb + (size_t)k * 128;
    float s = 0.f;
#pragma unroll 8
    for (int d = 0; d < 128; d++) s = fmaf(e[d], e[d], s);
    g_enorm[k] = s;
}

__global__ void fnorm_kernel() {
    int n = blockIdx.x * 256 + threadIdx.x;     // 8192 total
    const float* p = g_flat + (size_t)n * 128;
    float s = 0.f;
#pragma unroll 8
    for (int d = 0; d < 128; d++) s = fmaf(p[d], p[d], s);
    g_fnorm[n] = s;
}

__global__ void vq_reduce(float* __restrict__ codes_out) {
    int n = blockIdx.x * 256 + threadIdx.x;   // 8192 total
    float bv = g_pval[(size_t)n * 32];
    int   bi = g_pidx[(size_t)n * 32];
#pragma unroll
    for (int t = 1; t < 32; t++) {
        float v = g_pval[(size_t)n * 32 + t];
        int   i = g_pidx[(size_t)n * 32 + t];
        if (v < bv || (v == bv && i < bi)) { bv = v; bi = i; }
    }
    codes_out[n] = (float)bi;
}

// ---------------------------------------------------------------------------
extern "C" void kernel_launch(void* const* d_in, const int* in_sizes, int n_in,
                              void* d_out, int out_size) {
    const float* x   = (const float*)d_in[0];
    const float* w1  = (const float*)d_in[1];
    const float* b1  = (const float*)d_in[2];
    const float* w2  = (const float*)d_in[3];
    const float* b2  = (const float*)d_in[4];
    const float* w3  = (const float*)d_in[5];
    const float* b3  = (const float*)d_in[6];
    const float* w4  = (const float*)d_in[7];
    const float* b4  = (const float*)d_in[8];
    const float* g1  = (const float*)d_in[9];
    const float* be1 = (const float*)d_in[10];
    const float* m1  = (const float*)d_in[11];
    const float* v1  = (const float*)d_in[12];
    const float* g2  = (const float*)d_in[13];
    const float* be2 = (const float*)d_in[14];
    const float* m2  = (const float*)d_in[15];
    const float* v2  = (const float*)d_in[16];
    const float* g3  = (const float*)d_in[17];
    const float* be3 = (const float*)d_in[18];
    const float* m3  = (const float*)d_in[19];
    const float* v3  = (const float*)d_in[20];
    const float* g4  = (const float*)d_in[21];
    const float* be4 = (const float*)d_in[22];
    const float* m4  = (const float*)d_in[23];
    const float* v4  = (const float*)d_in[24];
    const float* emb = (const float*)d_in[25];

    void *p_h1, *p_h2, *p_h3, *p_flat, *p_dist_scr, *p_codes_scr;
    cudaGetSymbolAddress(&p_h1, g_h1);
    cudaGetSymbolAddress(&p_h2, g_h2);
    cudaGetSymbolAddress(&p_h3, g_h3);
    cudaGetSymbolAddress(&p_flat, g_flat);
    cudaGetSymbolAddress(&p_dist_scr, g_dist_scratch);
    cudaGetSymbolAddress(&p_codes_scr, g_codes_scratch);

    float* h1   = (float*)p_h1;
    float* h2   = (float*)p_h2;
    float* h3   = (float*)p_h3;
    float* flat = (float*)p_flat;

    // Output layout: reference returns (codes, dist). Default: codes||dist.
    float* out = (float*)d_out;
    float* codes_ptr;
    float* dist_ptr;
    const long long FULL = 8192LL + 8192LL * 4096LL;
    if ((long long)out_size >= FULL) {
        codes_ptr = out;
        dist_ptr  = out + 8192;
    } else if ((long long)out_size == 8192LL * 4096LL) {
        codes_ptr = (float*)p_codes_scr;
        dist_ptr  = out;
    } else {
        codes_ptr = out;
        dist_ptr  = (float*)p_dist_scr;
    }

    // Layer 1: 256 -> 256, L 2048 -> 1024, stride 2
    conv_mma<256, 256, 2048, 1024, 2, false>
        <<<dim3(256, 2), 256>>>(x, w1, b1, g1, be1, m1, v1, h1);
    // Layer 2: 256 -> 512, L 1024 -> 512, stride 2
    conv_mma<256, 512, 1024, 512, 2, false>
        <<<dim3(128, 4), 256>>>(h1, w2, b2, g2, be2, m2, v2, h2);
    // Layer 3: 512 -> 512, L 512 -> 256, stride 2
    conv_mma<512, 512, 512, 256, 2, false>
        <<<dim3(64, 4), 256>>>(h2, w3, b3, g3, be3, m3, v3, h3);
    // Layer 4: 512 -> 128, L 256 -> 256, stride 1, M=positions -> flat[n][d]
    conv_mma<512, 128, 256, 256, 1, true>
        <<<dim3(64, 1), 256>>>(h3, w4, b4, g4, be4, m4, v4, flat);

    enorm_kernel<<<16, 256>>>(emb);
    fnorm_kernel<<<32, 256>>>();

    vq_mma<<<dim3(32, 64), 256>>>(emb, dist_ptr);
    vq_reduce<<<32, 256>>>(codes_ptr);
}